// round 1
// baseline (speedup 1.0000x reference)
#include <cuda_runtime.h>
#include <math.h>

#define BB    32
#define CINC  128
#define HH    64
#define WW    64
#define COUTC 128
#define NK    4
#define HIDN  32
#define TEMPF 34.0f

#define CO_T  16       // couts per block
#define TILE  32       // spatial tile (32x32)
#define CCHUNK 8       // cin per smem chunk

// dynamic smem: weights [CIN*9][8] float2  +  input chunk [CCHUNK][34][34]
#define SW_FLOATS (2*CINC*9*8)          // 18432 floats (float2 x 9216)
#define SIN_FLOATS (CCHUNK*34*34)       // 9248 floats
#define SMEM_BYTES ((SW_FLOATS + SIN_FLOATS)*4)   // 110720 B

__device__ float g_context[BB*CINC];
__device__ float g_att[BB*NK];

typedef unsigned long long ull;

__device__ __forceinline__ ull pack_bcast(float v) {
    ull r; unsigned u = __float_as_uint(v);
    asm("mov.b64 %0, {%1, %2};" : "=l"(r) : "r"(u), "r"(u));
    return r;
}
__device__ __forceinline__ ull fma2(ull a, ull b, ull c) {
    ull d;
    asm("fma.rn.f32x2 %0, %1, %2, %3;" : "=l"(d) : "l"(a), "l"(b), "l"(c));
    return d;
}
__device__ __forceinline__ float2 unpack2(ull v) {
    unsigned lo, hi;
    asm("mov.b64 {%0, %1}, %2;" : "=r"(lo), "=r"(hi) : "l"(v));
    float2 f; f.x = __uint_as_float(lo); f.y = __uint_as_float(hi);
    return f;
}

// ---------------- Kernel 1: global average pool ----------------
__global__ void mean_kernel(const float* __restrict__ x) {
    int bc = blockIdx.x;                       // 0 .. B*CIN-1
    const float* p = x + (size_t)bc * (HH*WW);
    float s = 0.f;
    for (int i = threadIdx.x; i < HH*WW; i += 256) s += p[i];
    #pragma unroll
    for (int o = 16; o > 0; o >>= 1) s += __shfl_xor_sync(0xffffffffu, s, o);
    __shared__ float red[8];
    if ((threadIdx.x & 31) == 0) red[threadIdx.x >> 5] = s;
    __syncthreads();
    if (threadIdx.x < 8) {
        s = red[threadIdx.x];
        #pragma unroll
        for (int o = 4; o > 0; o >>= 1) s += __shfl_xor_sync(0xffu, s, o);
        if (threadIdx.x == 0) g_context[bc] = s * (1.0f / (HH*WW));
    }
}

// ---------------- Kernel 2: attention MLP + softmax ----------------
__global__ void att_kernel(const float* __restrict__ fc1_w,
                           const float* __restrict__ fc2_w,
                           const float* __restrict__ fc2_b) {
    int b = threadIdx.x;
    if (b >= BB) return;
    float hid[HIDN];
    #pragma unroll 4
    for (int h = 0; h < HIDN; ++h) {
        float s = 0.f;
        for (int c = 0; c < CINC; ++c) s += g_context[b*CINC + c] * fc1_w[h*CINC + c];
        hid[h] = fmaxf(s, 0.f);
    }
    float lg[NK]; float m = -1e30f;
    #pragma unroll
    for (int n = 0; n < NK; ++n) {
        float s = fc2_b[n];
        #pragma unroll
        for (int h = 0; h < HIDN; ++h) s += hid[h] * fc2_w[n*HIDN + h];
        lg[n] = s * (1.0f / TEMPF);
        m = fmaxf(m, lg[n]);
    }
    float sum = 0.f;
    #pragma unroll
    for (int n = 0; n < NK; ++n) { lg[n] = expf(lg[n] - m); sum += lg[n]; }
    float inv = 1.0f / sum;
    #pragma unroll
    for (int n = 0; n < NK; ++n) g_att[b*NK + n] = lg[n] * inv;
}

// ---------------- Kernel 3: dynamic conv, f32x2-packed direct conv ----------------
__global__ void __launch_bounds__(256)
conv_kernel(const float* __restrict__ x,
            const float* __restrict__ weight,
            const float* __restrict__ bias,
            float* __restrict__ out) {
    extern __shared__ float smem[];
    float2* s_w2 = (float2*)smem;                 // [(ci*9+t)*8 + cop]
    float*  s_in = smem + SW_FLOATS;              // [cc][34][34]

    const int b      = blockIdx.z;
    const int cobase = blockIdx.y * CO_T;
    const int tileY  = (blockIdx.x >> 1) * TILE;
    const int tileX  = (blockIdx.x & 1)  * TILE;
    const int tid    = threadIdx.x;

    float a[NK];
    #pragma unroll
    for (int k = 0; k < NK; ++k) a[k] = g_att[b*NK + k];

    // Aggregate this block's 16 couts worth of weights: sum_k att[b,k]*W[k]
    // smem layout pairs adjacent couts so compute can LDS.64 a packed pair.
    for (int idx2 = tid; idx2 < CINC*9*8; idx2 += 256) {
        int cir = idx2 >> 3;          // ci*9 + t  (0..1151)
        int cop = idx2 & 7;           // cout pair index
        const float* w0 = weight + (size_t)(cobase + 2*cop) * (CINC*9) + cir;
        float vx = 0.f, vy = 0.f;
        #pragma unroll
        for (int k = 0; k < NK; ++k) {
            vx += a[k] * w0[(size_t)k * (COUTC*CINC*9)];
            vy += a[k] * w0[(size_t)k * (COUTC*CINC*9) + CINC*9];
        }
        s_w2[idx2] = make_float2(vx, vy);
    }

    const float* xb = x + (size_t)b * (CINC*HH*WW);
    const int txi = tid & 15, tyi = tid >> 4;
    const int px = txi * 2, py = tyi * 2;

    ull acc[8][4];
    const ull z = pack_bcast(0.f);
    #pragma unroll
    for (int i = 0; i < 8; ++i)
        #pragma unroll
        for (int j = 0; j < 4; ++j) acc[i][j] = z;

    for (int cc0 = 0; cc0 < CINC; cc0 += CCHUNK) {
        __syncthreads();   // also covers weight-aggregation on first iteration
        // stage 8 input channels with halo, zero-padded
        for (int i = tid; i < CCHUNK*34*34; i += 256) {
            int cc  = i / 1156;
            int rem = i - cc * 1156;
            int iy  = rem / 34;
            int ix  = rem - iy * 34;
            int gy = tileY - 1 + iy, gx = tileX - 1 + ix;
            float v = 0.f;
            if ((unsigned)gy < (unsigned)HH && (unsigned)gx < (unsigned)WW)
                v = xb[(size_t)(cc0 + cc) * (HH*WW) + gy*WW + gx];
            s_in[i] = v;
        }
        __syncthreads();

        #pragma unroll
        for (int cc = 0; cc < CCHUNK; ++cc) {
            // 4x4 input patch, broadcast-packed into both f32x2 lanes
            ull v2[4][4];
            #pragma unroll
            for (int r = 0; r < 4; ++r)
                #pragma unroll
                for (int c = 0; c < 4; ++c)
                    v2[r][c] = pack_bcast(s_in[cc*1156 + (py + r)*34 + (px + c)]);

            const float2* wrow = s_w2 + (size_t)(cc0 + cc) * 9 * 8;
            #pragma unroll
            for (int cop = 0; cop < 8; ++cop) {
                ull w2[9];
                #pragma unroll
                for (int t = 0; t < 9; ++t)
                    w2[t] = *(const ull*)(wrow + (size_t)t*8 + cop);
                #pragma unroll
                for (int t = 0; t < 9; ++t) {
                    int dy = t / 3, dx = t - dy*3;
                    acc[cop][0] = fma2(v2[dy    ][dx    ], w2[t], acc[cop][0]);
                    acc[cop][1] = fma2(v2[dy    ][dx + 1], w2[t], acc[cop][1]);
                    acc[cop][2] = fma2(v2[dy + 1][dx    ], w2[t], acc[cop][2]);
                    acc[cop][3] = fma2(v2[dy + 1][dx + 1], w2[t], acc[cop][3]);
                }
            }
        }
    }

    // epilogue: unpack co-pairs, add aggregated bias, float2 stores
    #pragma unroll
    for (int cop = 0; cop < 8; ++cop) {
        float2 p0 = unpack2(acc[cop][0]);   // (co even, co odd) @ (sy0,sx0)
        float2 p1 = unpack2(acc[cop][1]);
        float2 p2 = unpack2(acc[cop][2]);
        float2 p3 = unpack2(acc[cop][3]);
        #pragma unroll
        for (int lane = 0; lane < 2; ++lane) {
            int co = cobase + 2*cop + lane;
            float bb = 0.f;
            #pragma unroll
            for (int k = 0; k < NK; ++k) bb += a[k] * bias[k*COUTC + co];
            float* op = out + ((size_t)(b*COUTC + co) * HH + (tileY + py)) * WW
                            + (tileX + px);
            float2 r0, r1;
            if (lane == 0) { r0.x = p0.x + bb; r0.y = p1.x + bb;
                             r1.x = p2.x + bb; r1.y = p3.x + bb; }
            else           { r0.x = p0.y + bb; r0.y = p1.y + bb;
                             r1.x = p2.y + bb; r1.y = p3.y + bb; }
            *(float2*)op        = r0;
            *(float2*)(op + WW) = r1;
        }
    }
}

extern "C" void kernel_launch(void* const* d_in, const int* in_sizes, int n_in,
                              void* d_out, int out_size) {
    const float* x     = (const float*)d_in[0];
    const float* fc1_w = (const float*)d_in[1];
    const float* fc2_w = (const float*)d_in[2];
    const float* fc2_b = (const float*)d_in[3];
    const float* weight= (const float*)d_in[4];
    const float* bias  = (const float*)d_in[5];
    float* out = (float*)d_out;

    cudaFuncSetAttribute(conv_kernel,
                         cudaFuncAttributeMaxDynamicSharedMemorySize, SMEM_BYTES);

    mean_kernel<<<BB*CINC, 256>>>(x);
    att_kernel<<<1, 32>>>(fc1_w, fc2_w, fc2_b);
    dim3 grid(4, COUTC/CO_T, BB);   // 2x2 spatial tiles, 8 cout tiles, 32 samples
    conv_kernel<<<grid, 256, SMEM_BYTES>>>(x, weight, bias, out);
}

// round 3
// speedup vs baseline: 1.9638x; 1.9638x over previous
#include <cuda_runtime.h>
#include <cuda_bf16.h>
#include <math.h>
#include <stdint.h>

#define BB    32
#define CINC  128
#define HH    64
#define WW    64
#define COUTC 128
#define NK    4
#define HIDN  32
#define TEMPF 34.0f

// halo-padded channel-last input: [B][66][66][CIN] bf16 (hi and lo split)
#define HP 66
__device__ __nv_bfloat16 g_xh[(size_t)BB*HP*HP*CINC];
__device__ __nv_bfloat16 g_xl[(size_t)BB*HP*HP*CINC];
// aggregated split weights: [B][9][COUT][CIN] bf16
__device__ __nv_bfloat16 g_wh[(size_t)BB*9*COUTC*CINC];
__device__ __nv_bfloat16 g_wl[(size_t)BB*9*COUTC*CINC];
__device__ float g_ctx[BB*CINC];
__device__ float g_att[BB*NK];
__device__ float g_aggb[BB*COUTC];

// ---------------- PTX helpers ----------------
__device__ __forceinline__ uint32_t smem_u32(const void* p) {
    uint32_t a;
    asm("{ .reg .u64 t; cvta.to.shared.u64 t, %1; cvt.u32.u64 %0, t; }" : "=r"(a) : "l"(p));
    return a;
}
#define SW128(off) ((off) ^ (((off) >> 3) & 0x70))

__device__ __forceinline__ void cp16(uint32_t dst, const void* src) {
    asm volatile("cp.async.cg.shared.global [%0], [%1], 16;" :: "r"(dst), "l"(src));
}
#define CP_COMMIT() asm volatile("cp.async.commit_group;" ::: "memory")
#define CP_WAIT1()  asm volatile("cp.async.wait_group 1;" ::: "memory")
#define CP_WAIT0()  asm volatile("cp.async.wait_group 0;" ::: "memory")

__device__ __forceinline__ void ldmx4(uint32_t* r, uint32_t addr) {
    asm volatile("ldmatrix.sync.aligned.m8n8.x4.shared.b16 {%0,%1,%2,%3}, [%4];"
                 : "=r"(r[0]), "=r"(r[1]), "=r"(r[2]), "=r"(r[3]) : "r"(addr));
}
__device__ __forceinline__ void mma_bf16(float* d, const uint32_t* a, const uint32_t* b) {
    asm volatile("mma.sync.aligned.m16n8k16.row.col.f32.bf16.bf16.f32 "
                 "{%0,%1,%2,%3}, {%4,%5,%6,%7}, {%8,%9}, {%0,%1,%2,%3};"
                 : "+f"(d[0]), "+f"(d[1]), "+f"(d[2]), "+f"(d[3])
                 : "r"(a[0]), "r"(a[1]), "r"(a[2]), "r"(a[3]), "r"(b[0]), "r"(b[1]));
}

// ---------------- Kernel 1: global average pool ----------------
__global__ void mean_kernel(const float* __restrict__ x) {
    int bc = blockIdx.x;
    const float4* p = (const float4*)(x + (size_t)bc * (HH*WW));
    float s = 0.f;
    #pragma unroll
    for (int i = 0; i < 4; ++i) {
        float4 v = p[threadIdx.x + i*256];
        s += v.x + v.y + v.z + v.w;
    }
    #pragma unroll
    for (int o = 16; o > 0; o >>= 1) s += __shfl_xor_sync(0xffffffffu, s, o);
    __shared__ float red[8];
    if ((threadIdx.x & 31) == 0) red[threadIdx.x >> 5] = s;
    __syncthreads();
    if (threadIdx.x < 8) {
        s = red[threadIdx.x];
        #pragma unroll
        for (int o = 4; o > 0; o >>= 1) s += __shfl_xor_sync(0xffu, s, o);
        if (threadIdx.x == 0) g_ctx[bc] = s * (1.0f / (HH*WW));
    }
}

// ---------------- Kernel 2: attention MLP + softmax + agg bias ----------------
__global__ void att_kernel(const float* __restrict__ fc1_w,
                           const float* __restrict__ fc2_w,
                           const float* __restrict__ fc2_b,
                           const float* __restrict__ bias) {
    int tid = threadIdx.x;
    if (tid < BB) {
        int b = tid;
        float hid[HIDN];
        #pragma unroll 4
        for (int h = 0; h < HIDN; ++h) {
            float s = 0.f;
            for (int c = 0; c < CINC; ++c) s += g_ctx[b*CINC + c] * fc1_w[h*CINC + c];
            hid[h] = fmaxf(s, 0.f);
        }
        float lg[NK]; float m = -1e30f;
        #pragma unroll
        for (int n = 0; n < NK; ++n) {
            float s = fc2_b[n];
            #pragma unroll
            for (int h = 0; h < HIDN; ++h) s += hid[h] * fc2_w[n*HIDN + h];
            lg[n] = s * (1.0f / TEMPF);
            m = fmaxf(m, lg[n]);
        }
        float sum = 0.f;
        #pragma unroll
        for (int n = 0; n < NK; ++n) { lg[n] = expf(lg[n] - m); sum += lg[n]; }
        float inv = 1.0f / sum;
        #pragma unroll
        for (int n = 0; n < NK; ++n) g_att[b*NK + n] = lg[n] * inv;
    }
    __syncthreads();
    int co = tid;  // 128 threads
    for (int b = 0; b < BB; ++b) {
        float s = 0.f;
        #pragma unroll
        for (int k = 0; k < NK; ++k) s += g_att[b*NK + k] * bias[k*COUTC + co];
        g_aggb[b*COUTC + co] = s;
    }
}

// ---------------- Kernel 3: zero halo borders ----------------
__global__ void halo_kernel() {
    int b = blockIdx.y, yy = blockIdx.x;
    bool full = (yy == 0 || yy == HP-1);
    int nsite = full ? HP : 2;
    for (int i = threadIdx.x; i < nsite*CINC; i += 256) {
        int si = i >> 7, ci = i & 127;
        int xx = full ? si : (si ? HP-1 : 0);
        size_t off = (((size_t)b*HP + yy)*HP + xx)*CINC + ci;
        g_xh[off] = __float2bfloat16(0.f);
        g_xl[off] = __float2bfloat16(0.f);
    }
}

// ---------------- Kernel 4: transpose+split x ----------------
__global__ void __launch_bounds__(256) prepx_kernel(const float* __restrict__ x) {
    __shared__ float tile[CINC][33];
    int x0 = blockIdx.x * 32, y = blockIdx.y, b = blockIdx.z;
    int tid = threadIdx.x;
    #pragma unroll
    for (int r = 0; r < 16; ++r) {
        int ci = r*8 + (tid >> 5), xp = tid & 31;
        tile[ci][xp] = x[(((size_t)b*CINC + ci)*HH + y)*WW + x0 + xp];
    }
    __syncthreads();
    int ci = tid & 127;
    #pragma unroll
    for (int r = 0; r < 16; ++r) {
        int xp = r*2 + (tid >> 7);
        float v = tile[ci][xp];
        __nv_bfloat16 hi = __float2bfloat16(v);
        __nv_bfloat16 lo = __float2bfloat16(v - __bfloat162float(hi));
        size_t off = (((size_t)b*HP + (y+1))*HP + (x0 + xp + 1))*CINC + ci;
        g_xh[off] = hi;
        g_xl[off] = lo;
    }
}

// ---------------- Kernel 5: aggregate + split weights ----------------
__global__ void __launch_bounds__(256) prepw_kernel(const float* __restrict__ weight) {
    int co = blockIdx.x, b = blockIdx.y;
    float a[NK];
    #pragma unroll
    for (int k = 0; k < NK; ++k) a[k] = g_att[b*NK + k];
    for (int idx = threadIdx.x; idx < 9*CINC; idx += 256) {
        int t = idx >> 7, ci = idx & 127;
        float s = 0.f;
        #pragma unroll
        for (int k = 0; k < NK; ++k)
            s += a[k] * weight[((size_t)(k*COUTC + co)*CINC + ci)*9 + t];
        __nv_bfloat16 hi = __float2bfloat16(s);
        __nv_bfloat16 lo = __float2bfloat16(s - __bfloat162float(hi));
        size_t off = (((size_t)(b*9 + t)*COUTC) + co)*CINC + ci;
        g_wh[off] = hi;
        g_wl[off] = lo;
    }
}

// ---------------- Kernel 6: HMMA bf16-split conv GEMM ----------------
// CTA: M=128 pixels (2 rows x 64), N=128 couts. 18 stages of K=64 (tap x ci-half).
// Double-buffered cp.async: each stage = 4 matrices (Ah, Al, Bh, Bl) of 16KB.
#define STAGE_B 65536            // 4 * 16384
#define SMEM_TOTAL 131072

__global__ void __launch_bounds__(256, 1) conv_kernel(float* __restrict__ out) {
    extern __shared__ __align__(1024) char smem[];
    const uint32_t sbase = smem_u32(smem);
    const int tid = threadIdx.x, wid = tid >> 5, lane = tid & 31;
    const int b = blockIdx.y;
    const int y0 = blockIdx.x * 2;

    const int warp_m = wid >> 1;          // 0..3 : pixel rows 32*warp_m
    const int warp_n = wid & 1;           // 0..1 : couts 64*warp_n

    // ldmatrix per-lane address components
    const int quad = lane >> 3, l7 = lane & 7;
    const int a_row_off = ((quad & 1) << 3) + l7;       // A: +0/+8 rows
    const int a_k_off   = (quad >> 1) << 4;             // A: +0/+16 bytes
    const int b_row_off = ((quad >> 1) << 3) + l7;      // B: +0/+8 rows
    const int b_k_off   = (quad & 1) << 4;              // B: +0/+16 bytes

    float acc[2][8][4];
    #pragma unroll
    for (int mi = 0; mi < 2; ++mi)
        #pragma unroll
        for (int nf = 0; nf < 8; ++nf)
            #pragma unroll
            for (int e = 0; e < 4; ++e) acc[mi][nf][e] = 0.f;

    // ---- stage issue: 4096 x 16B cp.async across 256 threads
    auto issue_stage = [&](int buf, int g) {
        const int tap = g >> 1, c2 = g & 1;
        const int dy = tap / 3, dx = tap % 3;
        const uint32_t sb = sbase + buf * STAGE_B;
        #pragma unroll
        for (int i = 0; i < 16; ++i) {
            int idx = tid + i*256;
            int mat = idx >> 10;
            int r   = (idx >> 3) & 127;
            int c8  = idx & 7;
            uint32_t dst = sb + mat*16384 + SW128(r*128 + c8*16);
            const char* src;
            if (mat < 2) {
                int pr = r >> 6, pc = r & 63;
                size_t e = (((size_t)b*HP + (y0 + pr + dy))*HP + (pc + dx))*CINC + c2*64;
                src = (const char*)(mat ? g_xl : g_xh) + e*2 + c8*16;
            } else {
                size_t e = (((size_t)(b*9 + tap))*COUTC + r)*CINC + c2*64;
                src = (const char*)(mat == 3 ? g_wl : g_wh) + e*2 + c8*16;
            }
            cp16(dst, src);
        }
    };

    // prologue
    issue_stage(0, 0);
    CP_COMMIT();

    for (int g = 0; g < 18; ++g) {
        __syncthreads();                    // everyone done computing stage g-1
        if (g + 1 < 18) {
            issue_stage((g + 1) & 1, g + 1);
            CP_COMMIT();
            CP_WAIT1();
        } else {
            CP_WAIT0();
        }
        __syncthreads();                    // stage g resident for all threads

        const uint32_t sb = sbase + (g & 1) * STAGE_B;
        const uint32_t ah_b = sb;
        const uint32_t al_b = sb + 16384;
        const uint32_t bh_b = sb + 2*16384;
        const uint32_t bl_b = sb + 3*16384;

        #pragma unroll
        for (int kc = 0; kc < 4; ++kc) {
            const int kb = kc * 32;
            uint32_t Ah[2][4], Al[2][4], Bh[4][4], Bl[4][4];
            #pragma unroll
            for (int mi = 0; mi < 2; ++mi) {
                int row = warp_m*32 + mi*16 + a_row_off;
                uint32_t off = SW128(row*128 + kb + a_k_off);
                ldmx4(Ah[mi], ah_b + off);
                ldmx4(Al[mi], al_b + off);
            }
            #pragma unroll
            for (int nj = 0; nj < 4; ++nj) {
                int row = warp_n*64 + nj*16 + b_row_off;
                uint32_t off = SW128(row*128 + kb + b_k_off);
                ldmx4(Bh[nj], bh_b + off);
                ldmx4(Bl[nj], bl_b + off);
            }
            #pragma unroll
            for (int mi = 0; mi < 2; ++mi)
                #pragma unroll
                for (int nf = 0; nf < 8; ++nf) {
                    const uint32_t* bh = &Bh[nf >> 1][(nf & 1) * 2];
                    const uint32_t* bl = &Bl[nf >> 1][(nf & 1) * 2];
                    mma_bf16(acc[mi][nf], Ah[mi], bh);   // hh
                    mma_bf16(acc[mi][nf], Al[mi], bh);   // lh
                    mma_bf16(acc[mi][nf], Ah[mi], bl);   // hl
                }
        }
    }

    // ---- epilogue: regs -> smem [co][p] -> coalesced gmem + bias
    __syncthreads();
    float* stage = (float*)smem;            // [128][132]
    #pragma unroll
    for (int mi = 0; mi < 2; ++mi)
        #pragma unroll
        for (int nf = 0; nf < 8; ++nf)
            #pragma unroll
            for (int e = 0; e < 4; ++e) {
                int p  = warp_m*32 + mi*16 + (lane >> 2) + ((e >> 1) << 3);
                int co = warp_n*64 + nf*8 + ((lane & 3) << 1) + (e & 1);
                stage[co*132 + p] = acc[mi][nf][e];
            }
    __syncthreads();
    #pragma unroll
    for (int i = 0; i < 64; ++i) {
        int idx = tid + i*256;
        int co = idx >> 7, p = idx & 127;
        float v = stage[co*132 + p] + g_aggb[b*COUTC + co];
        out[(((size_t)b*COUTC + co)*HH + y0 + (p >> 6))*WW + (p & 63)] = v;
    }
}

extern "C" void kernel_launch(void* const* d_in, const int* in_sizes, int n_in,
                              void* d_out, int out_size) {
    const float* x      = (const float*)d_in[0];
    const float* fc1_w  = (const float*)d_in[1];
    const float* fc2_w  = (const float*)d_in[2];
    const float* fc2_b  = (const float*)d_in[3];
    const float* weight = (const float*)d_in[4];
    const float* bias   = (const float*)d_in[5];
    float* out = (float*)d_out;

    cudaFuncSetAttribute(conv_kernel,
                         cudaFuncAttributeMaxDynamicSharedMemorySize, SMEM_TOTAL);

    halo_kernel<<<dim3(HP, BB), 256>>>();
    prepx_kernel<<<dim3(2, HH, BB), 256>>>(x);
    mean_kernel<<<BB*CINC, 256>>>(x);
    att_kernel<<<1, 128>>>(fc1_w, fc2_w, fc2_b, bias);
    prepw_kernel<<<dim3(COUTC, BB), 256>>>(weight);
    conv_kernel<<<dim3(HH/2, BB), 256, SMEM_TOTAL>>>(out);
}

// round 5
// speedup vs baseline: 2.9063x; 1.4800x over previous
#include <cuda_runtime.h>
#include <cuda_bf16.h>
#include <math.h>
#include <stdint.h>

#define BB    32
#define CINC  128
#define HH    64
#define WW    64
#define COUTC 128
#define NK    4
#define HIDN  32
#define TEMPF 34.0f

// halo-padded channel-last input: [B][66][66][CIN] bf16 (hi and lo split)
#define HP 66
__device__ __nv_bfloat16 g_xh[(size_t)BB*HP*HP*CINC];
__device__ __nv_bfloat16 g_xl[(size_t)BB*HP*HP*CINC];
// aggregated split weights: [B][9][COUT][CIN] bf16
__device__ __nv_bfloat16 g_wh[(size_t)BB*9*COUTC*CINC];
__device__ __nv_bfloat16 g_wl[(size_t)BB*9*COUTC*CINC];
__device__ float g_ctx[BB*CINC];
__device__ float g_att[BB*NK];
__device__ float g_aggb[BB*COUTC];

// ---------------- PTX helpers ----------------
__device__ __forceinline__ uint32_t smem_u32(const void* p) {
    uint32_t a;
    asm("{ .reg .u64 t; cvta.to.shared.u64 t, %1; cvt.u32.u64 %0, t; }" : "=r"(a) : "l"(p));
    return a;
}
#define SW128(off) ((off) ^ (((off) >> 3) & 0x70))

__device__ __forceinline__ void cp16(uint32_t dst, const void* src) {
    asm volatile("cp.async.cg.shared.global [%0], [%1], 16;" :: "r"(dst), "l"(src));
}
#define CP_COMMIT() asm volatile("cp.async.commit_group;" ::: "memory")
#define CP_WAIT1()  asm volatile("cp.async.wait_group 1;" ::: "memory")
#define CP_WAIT0()  asm volatile("cp.async.wait_group 0;" ::: "memory")

__device__ __forceinline__ void ldmx4(uint32_t* r, uint32_t addr) {
    asm volatile("ldmatrix.sync.aligned.m8n8.x4.shared.b16 {%0,%1,%2,%3}, [%4];"
                 : "=r"(r[0]), "=r"(r[1]), "=r"(r[2]), "=r"(r[3]) : "r"(addr));
}
__device__ __forceinline__ void mma_bf16(float* d, const uint32_t* a, const uint32_t* b) {
    asm volatile("mma.sync.aligned.m16n8k16.row.col.f32.bf16.bf16.f32 "
                 "{%0,%1,%2,%3}, {%4,%5,%6,%7}, {%8,%9}, {%0,%1,%2,%3};"
                 : "+f"(d[0]), "+f"(d[1]), "+f"(d[2]), "+f"(d[3])
                 : "r"(a[0]), "r"(a[1]), "r"(a[2]), "r"(a[3]), "r"(b[0]), "r"(b[1]));
}

// ---------------- Kernel 1: global average pool ----------------
__global__ void mean_kernel(const float* __restrict__ x) {
    int bc = blockIdx.x;
    const float4* p = (const float4*)(x + (size_t)bc * (HH*WW));
    float s = 0.f;
    #pragma unroll
    for (int i = 0; i < 4; ++i) {
        float4 v = p[threadIdx.x + i*256];
        s += v.x + v.y + v.z + v.w;
    }
    #pragma unroll
    for (int o = 16; o > 0; o >>= 1) s += __shfl_xor_sync(0xffffffffu, s, o);
    __shared__ float red[8];
    if ((threadIdx.x & 31) == 0) red[threadIdx.x >> 5] = s;
    __syncthreads();
    if (threadIdx.x < 8) {
        s = red[threadIdx.x];
        #pragma unroll
        for (int o = 4; o > 0; o >>= 1) s += __shfl_xor_sync(0xffu, s, o);
        if (threadIdx.x == 0) g_ctx[bc] = s * (1.0f / (HH*WW));
    }
}

// ---------------- Kernel 2: attention MLP + softmax + agg bias ----------------
// one block per sample, warp-parallel dot products
__global__ void __launch_bounds__(128) att_kernel(const float* __restrict__ fc1_w,
                                                  const float* __restrict__ fc2_w,
                                                  const float* __restrict__ fc2_b,
                                                  const float* __restrict__ bias) {
    const int b = blockIdx.x;
    const int tid = threadIdx.x, wid = tid >> 5, lane = tid & 31;
    __shared__ float s_ctx[CINC];
    __shared__ float s_hid[HIDN];
    __shared__ float s_att[NK];

    s_ctx[tid] = g_ctx[b*CINC + tid];
    __syncthreads();

    // hid[h]: 4 warps x 8 h each; lane-parallel over 128 c (4 per lane)
    #pragma unroll
    for (int i = 0; i < 8; ++i) {
        int h = wid*8 + i;
        float s = 0.f;
        #pragma unroll
        for (int j = 0; j < 4; ++j) {
            int c = lane + j*32;
            s += s_ctx[c] * fc1_w[h*CINC + c];
        }
        #pragma unroll
        for (int o = 16; o > 0; o >>= 1) s += __shfl_xor_sync(0xffffffffu, s, o);
        if (lane == 0) s_hid[h] = fmaxf(s, 0.f);
    }
    __syncthreads();

    // logits + softmax: warp 0, lane-groups of 8 per k
    if (wid == 0) {
        int k = lane >> 3, l8 = lane & 7;
        float s = 0.f;
        #pragma unroll
        for (int j = 0; j < 4; ++j) {
            int h = l8 + j*8;
            s += s_hid[h] * fc2_w[k*HIDN + h];
        }
        #pragma unroll
        for (int o = 4; o > 0; o >>= 1) s += __shfl_xor_sync(0xffffffffu, s, o);
        s += fc2_b[k];
        float lg = s * (1.0f / TEMPF);
        // softmax across the 4 k-group leaders (lanes 0,8,16,24)
        float m = lg;
        #pragma unroll
        for (int o = 16; o >= 8; o >>= 1) m = fmaxf(m, __shfl_xor_sync(0xffffffffu, m, o));
        float e = expf(lg - m);
        float sum = e;
        #pragma unroll
        for (int o = 16; o >= 8; o >>= 1) sum += __shfl_xor_sync(0xffffffffu, sum, o);
        if (l8 == 0) {
            float a = e / sum;
            s_att[k] = a;
            g_att[b*NK + k] = a;
        }
    }
    __syncthreads();

    // aggregated bias for this sample
    float sb = 0.f;
    #pragma unroll
    for (int k = 0; k < NK; ++k) sb += s_att[k] * bias[k*COUTC + tid];
    g_aggb[b*COUTC + tid] = sb;
}

// ---------------- Kernel 3: zero halo borders ----------------
__global__ void halo_kernel() {
    int b = blockIdx.y, yy = blockIdx.x;
    bool full = (yy == 0 || yy == HP-1);
    int nsite = full ? HP : 2;
    for (int i = threadIdx.x; i < nsite*CINC; i += 256) {
        int si = i >> 7, ci = i & 127;
        int xx = full ? si : (si ? HP-1 : 0);
        size_t off = (((size_t)b*HP + yy)*HP + xx)*CINC + ci;
        g_xh[off] = __float2bfloat16(0.f);
        g_xl[off] = __float2bfloat16(0.f);
    }
}

// ---------------- Kernel 4: transpose+split x ----------------
__global__ void __launch_bounds__(256) prepx_kernel(const float* __restrict__ x) {
    __shared__ float tile[CINC][33];
    int x0 = blockIdx.x * 32, y = blockIdx.y, b = blockIdx.z;
    int tid = threadIdx.x;
    #pragma unroll
    for (int r = 0; r < 16; ++r) {
        int ci = r*8 + (tid >> 5), xp = tid & 31;
        tile[ci][xp] = x[(((size_t)b*CINC + ci)*HH + y)*WW + x0 + xp];
    }
    __syncthreads();
    int ci = tid & 127;
    #pragma unroll
    for (int r = 0; r < 16; ++r) {
        int xp = r*2 + (tid >> 7);
        float v = tile[ci][xp];
        __nv_bfloat16 hi = __float2bfloat16(v);
        __nv_bfloat16 lo = __float2bfloat16(v - __bfloat162float(hi));
        size_t off = (((size_t)b*HP + (y+1))*HP + (x0 + xp + 1))*CINC + ci;
        g_xh[off] = hi;
        g_xl[off] = lo;
    }
}

// ---------------- Kernel 5: aggregate + split weights ----------------
__global__ void __launch_bounds__(256) prepw_kernel(const float* __restrict__ weight) {
    int co = blockIdx.x, b = blockIdx.y;
    float a[NK];
    #pragma unroll
    for (int k = 0; k < NK; ++k) a[k] = g_att[b*NK + k];
    for (int idx = threadIdx.x; idx < 9*CINC; idx += 256) {
        int t = idx >> 7, ci = idx & 127;
        float s = 0.f;
        #pragma unroll
        for (int k = 0; k < NK; ++k)
            s += a[k] * weight[((size_t)(k*COUTC + co)*CINC + ci)*9 + t];
        __nv_bfloat16 hi = __float2bfloat16(s);
        __nv_bfloat16 lo = __float2bfloat16(s - __bfloat162float(hi));
        size_t off = (((size_t)(b*9 + t)*COUTC) + co)*CINC + ci;
        g_wh[off] = hi;
        g_wl[off] = lo;
    }
}

// ---------------- Kernel 6: HMMA bf16-split conv GEMM ----------------
// CTA: M=128 pixels (2 rows x 64), N=128 couts. 18 stages of K=64 (tap x ci-half).
// Double-buffered cp.async: each stage = 4 matrices (Ah, Al, Bh, Bl) of 16KB.
#define STAGE_B 65536            // 4 * 16384
#define SMEM_TOTAL 131072

__global__ void __launch_bounds__(256, 1) conv_kernel(float* __restrict__ out) {
    extern __shared__ __align__(1024) char smem[];
    const uint32_t sbase = smem_u32(smem);
    const int tid = threadIdx.x, wid = tid >> 5, lane = tid & 31;
    const int b = blockIdx.y;
    const int y0 = blockIdx.x * 2;

    const int warp_m = wid >> 1;          // 0..3 : pixel rows 32*warp_m
    const int warp_n = wid & 1;           // 0..1 : couts 64*warp_n

    const int quad = lane >> 3, l7 = lane & 7;
    const int a_row_off = ((quad & 1) << 3) + l7;
    const int a_k_off   = (quad >> 1) << 4;
    const int b_row_off = ((quad >> 1) << 3) + l7;
    const int b_k_off   = (quad & 1) << 4;

    float acc[2][8][4];
    #pragma unroll
    for (int mi = 0; mi < 2; ++mi)
        #pragma unroll
        for (int nf = 0; nf < 8; ++nf)
            #pragma unroll
            for (int e = 0; e < 4; ++e) acc[mi][nf][e] = 0.f;

    auto issue_stage = [&](int buf, int g) {
        const int tap = g >> 1, c2 = g & 1;
        const int dy = tap / 3, dx = tap % 3;
        const uint32_t sb = sbase + buf * STAGE_B;
        #pragma unroll
        for (int i = 0; i < 16; ++i) {
            int idx = tid + i*256;
            int mat = idx >> 10;
            int r   = (idx >> 3) & 127;
            int c8  = idx & 7;
            uint32_t dst = sb + mat*16384 + SW128(r*128 + c8*16);
            const char* src;
            if (mat < 2) {
                int pr = r >> 6, pc = r & 63;
                size_t e = (((size_t)b*HP + (y0 + pr + dy))*HP + (pc + dx))*CINC + c2*64;
                src = (const char*)(mat ? g_xl : g_xh) + e*2 + c8*16;
            } else {
                size_t e = (((size_t)(b*9 + tap))*COUTC + r)*CINC + c2*64;
                src = (const char*)(mat == 3 ? g_wl : g_wh) + e*2 + c8*16;
            }
            cp16(dst, src);
        }
    };

    issue_stage(0, 0);
    CP_COMMIT();

    for (int g = 0; g < 18; ++g) {
        __syncthreads();
        if (g + 1 < 18) {
            issue_stage((g + 1) & 1, g + 1);
            CP_COMMIT();
            CP_WAIT1();
        } else {
            CP_WAIT0();
        }
        __syncthreads();

        const uint32_t sb = sbase + (g & 1) * STAGE_B;
        const uint32_t ah_b = sb;
        const uint32_t al_b = sb + 16384;
        const uint32_t bh_b = sb + 2*16384;
        const uint32_t bl_b = sb + 3*16384;

        #pragma unroll
        for (int kc = 0; kc < 4; ++kc) {
            const int kb = kc * 32;
            uint32_t Ah[2][4], Al[2][4], Bh[4][4], Bl[4][4];
            #pragma unroll
            for (int mi = 0; mi < 2; ++mi) {
                int row = warp_m*32 + mi*16 + a_row_off;
                uint32_t off = SW128(row*128 + kb + a_k_off);
                ldmx4(Ah[mi], ah_b + off);
                ldmx4(Al[mi], al_b + off);
            }
            #pragma unroll
            for (int nj = 0; nj < 4; ++nj) {
                int row = warp_n*64 + nj*16 + b_row_off;
                uint32_t off = SW128(row*128 + kb + b_k_off);
                ldmx4(Bh[nj], bh_b + off);
                ldmx4(Bl[nj], bl_b + off);
            }
            #pragma unroll
            for (int mi = 0; mi < 2; ++mi)
                #pragma unroll
                for (int nf = 0; nf < 8; ++nf) {
                    const uint32_t* bh = &Bh[nf >> 1][(nf & 1) * 2];
                    const uint32_t* bl = &Bl[nf >> 1][(nf & 1) * 2];
                    mma_bf16(acc[mi][nf], Ah[mi], bh);   // hh
                    mma_bf16(acc[mi][nf], Al[mi], bh);   // lh
                    mma_bf16(acc[mi][nf], Ah[mi], bl);   // hl
                }
        }
    }

    // ---- epilogue: regs -> smem [co][p] -> coalesced gmem + bias
    __syncthreads();
    float* stage = (float*)smem;            // [128][132]
    #pragma unroll
    for (int mi = 0; mi < 2; ++mi)
        #pragma unroll
        for (int nf = 0; nf < 8; ++nf)
            #pragma unroll
            for (int e = 0; e < 4; ++e) {
                int p  = warp_m*32 + mi*16 + (lane >> 2) + ((e >> 1) << 3);
                int co = warp_n*64 + nf*8 + ((lane & 3) << 1) + (e & 1);
                stage[co*132 + p] = acc[mi][nf][e];
            }
    __syncthreads();
    #pragma unroll
    for (int i = 0; i < 64; ++i) {
        int idx = tid + i*256;
        int co = idx >> 7, p = idx & 127;
        float v = stage[co*132 + p] + g_aggb[b*COUTC + co];
        out[(((size_t)b*COUTC + co)*HH + y0 + (p >> 6))*WW + (p & 63)] = v;
    }
}

extern "C" void kernel_launch(void* const* d_in, const int* in_sizes, int n_in,
                              void* d_out, int out_size) {
    const float* x      = (const float*)d_in[0];
    const float* fc1_w  = (const float*)d_in[1];
    const float* fc2_w  = (const float*)d_in[2];
    const float* fc2_b  = (const float*)d_in[3];
    const float* weight = (const float*)d_in[4];
    const float* bias   = (const float*)d_in[5];
    float* out = (float*)d_out;

    cudaFuncSetAttribute(conv_kernel,
                         cudaFuncAttributeMaxDynamicSharedMemorySize, SMEM_TOTAL);

    mean_kernel<<<BB*CINC, 256>>>(x);
    att_kernel<<<BB, 128>>>(fc1_w, fc2_w, fc2_b, bias);
    halo_kernel<<<dim3(HP, BB), 256>>>();
    prepx_kernel<<<dim3(2, HH, BB), 256>>>(x);
    prepw_kernel<<<dim3(COUTC, BB), 256>>>(weight);
    conv_kernel<<<dim3(HH/2, BB), 256, SMEM_TOTAL>>>(out);
}